// round 3
// baseline (speedup 1.0000x reference)
#include <cuda_runtime.h>
#include <math.h>

#define Bq 2
#define NQ 1600
#define D 256
#define NH 8
#define HD 32
#define NL 4
#define NP 4
#define DFFN 1024
#define S_TOT 5440
#define NLAYERS 6
#define M_Q (Bq*NQ)      /* 3200 */
#define M_S (Bq*S_TOT)   /* 10880 */

// ---------------- scratch (device globals; no allocations allowed) ----------
__device__ float g_x[M_Q*D];
__device__ float g_q[M_Q*D];
__device__ float g_pq[M_Q*D];
__device__ float g_pk[M_Q*D];
__device__ float g_pv[M_Q*D];
__device__ float g_ao[M_Q*D];
__device__ float g_t2[M_Q*D];
__device__ float g_off[M_Q*D];
__device__ float g_aw[M_Q*NH*NL*NP];
__device__ float g_val[M_S*D];
__device__ float g_ffn[M_Q*DFFN];
__device__ float g_scores[(size_t)Bq*NH*NQ*NQ];  // 40.96M floats

// ---------------- elementwise add ----------------
__global__ void add_kernel(const float* __restrict__ a, const float* __restrict__ b,
                           float* __restrict__ o, int n) {
    int i = blockIdx.x * blockDim.x + threadIdx.x;
    if (i < n) o[i] = a[i] + b[i];
}

// ---------------- generic SGEMM: C[M,N] = A[M,K] @ W[N,K]^T + bias, opt relu --
// BM=BN=64, BK=16, 256 threads, 4x4 per thread. M%64==0, N%64==0, K%16==0.
__global__ void gemm_bias_kernel(const float* __restrict__ A, const float* __restrict__ W,
                                 const float* __restrict__ bias, float* __restrict__ C,
                                 int M, int N, int K, int relu) {
    __shared__ float As[16][64];
    __shared__ float Ws[16][64];
    int bm = blockIdx.y * 64, bn = blockIdx.x * 64;
    int tid = threadIdx.x;
    int tx = tid & 15, ty = tid >> 4;
    int lk = tid & 15, lm = tid >> 4;
    float c[4][4] = {};
    for (int k0 = 0; k0 < K; k0 += 16) {
        #pragma unroll
        for (int i = 0; i < 4; i++) {
            As[lk][lm + 16*i] = A[(size_t)(bm + lm + 16*i) * K + k0 + lk];
            Ws[lk][lm + 16*i] = W[(size_t)(bn + lm + 16*i) * K + k0 + lk];
        }
        __syncthreads();
        #pragma unroll
        for (int k = 0; k < 16; k++) {
            float a[4], b[4];
            #pragma unroll
            for (int i = 0; i < 4; i++) { a[i] = As[k][ty*4 + i]; b[i] = Ws[k][tx*4 + i]; }
            #pragma unroll
            for (int i = 0; i < 4; i++)
                #pragma unroll
                for (int j = 0; j < 4; j++) c[i][j] = fmaf(a[i], b[j], c[i][j]);
        }
        __syncthreads();
    }
    #pragma unroll
    for (int i = 0; i < 4; i++) {
        int row = bm + ty*4 + i;
        #pragma unroll
        for (int j = 0; j < 4; j++) {
            int col = bn + tx*4 + j;
            float v = c[i][j] + bias[col];
            if (relu) v = fmaxf(v, 0.f);
            C[(size_t)row * N + col] = v;
        }
    }
}

// ---------------- attention scores: S[bh,i,j] = q.k / sqrt(32) ----------------
__global__ void attn_scores_kernel(const float* __restrict__ q, const float* __restrict__ k,
                                   float* __restrict__ scores) {
    int bh = blockIdx.z; int b = bh / NH; int h = bh % NH;
    int i0 = blockIdx.y * 64, j0 = blockIdx.x * 64;
    __shared__ float Qs[32][65];
    __shared__ float Ks[32][65];
    int tid = threadIdx.x;
    int lkk = tid & 31, lr = tid >> 5;
    const float* qb = q + (size_t)b * NQ * D + h * HD;
    const float* kb = k + (size_t)b * NQ * D + h * HD;
    #pragma unroll
    for (int r = 0; r < 8; r++) {
        Qs[lkk][lr + 8*r] = qb[(size_t)(i0 + lr + 8*r) * D + lkk];
        Ks[lkk][lr + 8*r] = kb[(size_t)(j0 + lr + 8*r) * D + lkk];
    }
    __syncthreads();
    int tx = tid & 15, ty = tid >> 4;
    float c[4][4] = {};
    #pragma unroll
    for (int kk = 0; kk < 32; kk++) {
        float a[4], bb[4];
        #pragma unroll
        for (int i = 0; i < 4; i++) { a[i] = Qs[kk][ty*4 + i]; bb[i] = Ks[kk][tx*4 + i]; }
        #pragma unroll
        for (int i = 0; i < 4; i++)
            #pragma unroll
            for (int j = 0; j < 4; j++) c[i][j] = fmaf(a[i], bb[j], c[i][j]);
    }
    const float scale = 0.17677669529663687f;  // 1/sqrt(32)
    float* sb = scores + (size_t)bh * NQ * NQ;
    #pragma unroll
    for (int i = 0; i < 4; i++)
        #pragma unroll
        for (int j = 0; j < 4; j++)
            sb[(size_t)(i0 + ty*4 + i) * NQ + j0 + tx*4 + j] = c[i][j] * scale;
}

// ---------------- row softmax over 1600 cols ----------------
__global__ void softmax_kernel(float* __restrict__ s, int cols) {
    size_t row = blockIdx.x;
    float* r = s + row * (size_t)cols;
    int tid = threadIdx.x;
    __shared__ float redA[8];
    __shared__ float redB[8];
    float m = -1e30f;
    for (int c = tid; c < cols; c += 256) m = fmaxf(m, r[c]);
    #pragma unroll
    for (int o = 16; o > 0; o >>= 1) m = fmaxf(m, __shfl_xor_sync(0xffffffffu, m, o));
    if ((tid & 31) == 0) redA[tid >> 5] = m;
    __syncthreads();
    float mm = redA[0];
    #pragma unroll
    for (int i = 1; i < 8; i++) mm = fmaxf(mm, redA[i]);
    float sum = 0.f;
    for (int c = tid; c < cols; c += 256) { float e = __expf(r[c] - mm); r[c] = e; sum += e; }
    #pragma unroll
    for (int o = 16; o > 0; o >>= 1) sum += __shfl_xor_sync(0xffffffffu, sum, o);
    if ((tid & 31) == 0) redB[tid >> 5] = sum;
    __syncthreads();
    float tot = 0.f;
    #pragma unroll
    for (int i = 0; i < 8; i++) tot += redB[i];
    float inv = 1.f / tot;
    for (int c = tid; c < cols; c += 256) r[c] *= inv;
}

// ---------------- attention PV: out = P @ V ----------------
__global__ void attn_pv_kernel(const float* __restrict__ p, const float* __restrict__ v,
                               float* __restrict__ out) {
    int bh = blockIdx.y; int b = bh / NH; int h = bh % NH;
    int i0 = blockIdx.x * 64;
    __shared__ float Ps[64][33];
    __shared__ float Vs[32][33];
    const float* pb = p + ((size_t)bh * NQ + i0) * NQ;
    const float* vb = v + (size_t)b * NQ * D + h * HD;
    int tid = threadIdx.x;
    int d = tid & 31, ib = tid >> 5;
    float acc[8] = {};
    for (int j0 = 0; j0 < NQ; j0 += 32) {
        int lj = tid & 31, li = tid >> 5;
        #pragma unroll
        for (int r = 0; r < 8; r++) Ps[li + 8*r][lj] = pb[(size_t)(li + 8*r) * NQ + j0 + lj];
        #pragma unroll
        for (int r = 0; r < 4; r++) Vs[li + 8*r][lj] = vb[(size_t)(j0 + li + 8*r) * D + lj];
        __syncthreads();
        #pragma unroll
        for (int j = 0; j < 32; j++) {
            float vv = Vs[j][d];
            #pragma unroll
            for (int r = 0; r < 8; r++) acc[r] = fmaf(Ps[ib + 8*r][j], vv, acc[r]);
        }
        __syncthreads();
    }
    float* ob = out + (size_t)b * NQ * D + h * HD;
    #pragma unroll
    for (int r = 0; r < 8; r++) ob[(size_t)(i0 + ib + 8*r) * D + d] = acc[r];
}

// ---------------- residual + layernorm: out = LN(x + t) * g + b ----------------
__global__ void ln_residual_kernel(const float* __restrict__ x, const float* __restrict__ t,
                                   const float* __restrict__ gam, const float* __restrict__ bet,
                                   float* __restrict__ out) {
    int row = blockIdx.x;
    int c = threadIdx.x;  // 256 threads = D
    float v = x[(size_t)row * D + c] + t[(size_t)row * D + c];
    __shared__ float redA[8];
    __shared__ float redB[8];
    float s = v;
    #pragma unroll
    for (int o = 16; o > 0; o >>= 1) s += __shfl_xor_sync(0xffffffffu, s, o);
    if ((c & 31) == 0) redA[c >> 5] = s;
    __syncthreads();
    float mu = 0.f;
    #pragma unroll
    for (int i = 0; i < 8; i++) mu += redA[i];
    mu *= (1.f / D);
    float dv = v - mu;
    float sq = dv * dv;
    #pragma unroll
    for (int o = 16; o > 0; o >>= 1) sq += __shfl_xor_sync(0xffffffffu, sq, o);
    if ((c & 31) == 0) redB[c >> 5] = sq;
    __syncthreads();
    float var = 0.f;
    #pragma unroll
    for (int i = 0; i < 8; i++) var += redB[i];
    var *= (1.f / D);
    out[(size_t)row * D + c] = dv * rsqrtf(var + 1e-5f) * gam[c] + bet[c];
}

// ---------------- multi-scale deformable sampling ----------------
// grid = M_Q blocks, 256 threads = 8 warps (one per head), lane = channel
__global__ void ms_deform_kernel(const float* __restrict__ off, const float* __restrict__ aw_raw,
                                 const float* __restrict__ value, const float* __restrict__ refp,
                                 float* __restrict__ out) {
    const int lvl_start[4] = {0, 4096, 5120, 5376};
    const int lvl_w[4] = {64, 32, 16, 8};
    int row = blockIdx.x;
    int b = row / NQ; int q = row % NQ;
    int tid = threadIdx.x;
    int h = tid >> 5, lane = tid & 31;
    // softmax of aw over 16 (L*P) per head, via warp shuffles
    const float* awr = aw_raw + (size_t)row * (NH * 16) + h * 16;
    float a = (lane < 16) ? awr[lane] : -1e30f;
    float m = a;
    #pragma unroll
    for (int o = 16; o > 0; o >>= 1) m = fmaxf(m, __shfl_xor_sync(0xffffffffu, m, o));
    float e = (lane < 16) ? __expf(a - m) : 0.f;
    float ssum = e;
    #pragma unroll
    for (int o = 16; o > 0; o >>= 1) ssum += __shfl_xor_sync(0xffffffffu, ssum, o);
    float awn = e / ssum;
    const float* offr = off + (size_t)row * D + h * (NL * NP * 2);
    float acc = 0.f;
    #pragma unroll
    for (int l = 0; l < NL; l++) {
        int Wl = lvl_w[l]; int Hl = Wl;
        float rx = refp[(((size_t)b * NQ + q) * NL + l) * 2 + 0];
        float ry = refp[(((size_t)b * NQ + q) * NL + l) * 2 + 1];
        const float* vbase = value + ((size_t)b * S_TOT + lvl_start[l]) * D + h * HD + lane;
        #pragma unroll
        for (int p = 0; p < NP; p++) {
            float ox = offr[(l * NP + p) * 2 + 0];
            float oy = offr[(l * NP + p) * 2 + 1];
            float xx = (rx + ox / (float)Wl) * (float)Wl - 0.5f;
            float yy = (ry + oy / (float)Hl) * (float)Hl - 0.5f;
            float x0f = floorf(xx), y0f = floorf(yy);
            int x0 = (int)x0f, y0 = (int)y0f;
            float wx1 = xx - x0f, wy1 = yy - y0f;
            float pv = 0.f;
            #pragma unroll
            for (int dy = 0; dy < 2; dy++) {
                #pragma unroll
                for (int dx = 0; dx < 2; dx++) {
                    int xi = x0 + dx, yi = y0 + dy;
                    float w = (dx ? wx1 : 1.f - wx1) * (dy ? wy1 : 1.f - wy1);
                    if (xi >= 0 && xi < Wl && yi >= 0 && yi < Hl)
                        pv = fmaf(w, vbase[(size_t)(yi * Wl + xi) * D], pv);
                }
            }
            float awv = __shfl_sync(0xffffffffu, awn, l * NP + p);
            acc = fmaf(pv, awv, acc);
        }
    }
    out[(size_t)row * D + h * HD + lane] = acc;
}

// ---------------- host orchestration ----------------
static inline void gemm(const float* A, const float* W, const float* bias, float* C,
                        int M, int N, int K, int relu) {
    dim3 grid(N / 64, M / 64);
    gemm_bias_kernel<<<grid, 256>>>(A, W, bias, C, M, N, K, relu);
}

extern "C" void kernel_launch(void* const* d_in, const int* in_sizes, int n_in,
                              void* d_out, int out_size) {
    const float* tgt   = (const float*)d_in[0];
    const float* qpos  = (const float*)d_in[1];
    const float* refp  = (const float*)d_in[2];
    const float* src   = (const float*)d_in[3];
    const float* sa_w_q = (const float*)d_in[4];
    const float* sa_b_q = (const float*)d_in[5];
    const float* sa_w_k = (const float*)d_in[6];
    const float* sa_b_k = (const float*)d_in[7];
    const float* sa_w_v = (const float*)d_in[8];
    const float* sa_b_v = (const float*)d_in[9];
    const float* sa_w_o = (const float*)d_in[10];
    const float* sa_b_o = (const float*)d_in[11];
    const float* ln2_g  = (const float*)d_in[12];
    const float* ln2_b  = (const float*)d_in[13];
    const float* ca_w_off  = (const float*)d_in[14];
    const float* ca_b_off  = (const float*)d_in[15];
    const float* ca_w_attn = (const float*)d_in[16];
    const float* ca_b_attn = (const float*)d_in[17];
    const float* ca_w_val  = (const float*)d_in[18];
    const float* ca_b_val  = (const float*)d_in[19];
    const float* ca_w_out  = (const float*)d_in[20];
    const float* ca_b_out  = (const float*)d_in[21];
    const float* ln1_g  = (const float*)d_in[22];
    const float* ln1_b  = (const float*)d_in[23];
    const float* ffn_w1 = (const float*)d_in[24];
    const float* ffn_b1 = (const float*)d_in[25];
    const float* ffn_w2 = (const float*)d_in[26];
    const float* ffn_b2 = (const float*)d_in[27];
    const float* ln3_g  = (const float*)d_in[28];
    const float* ln3_b  = (const float*)d_in[29];

    float *p_x, *p_q, *p_pq, *p_pk, *p_pv, *p_ao, *p_t2, *p_off, *p_aw, *p_val, *p_ffn, *p_sc;
    cudaGetSymbolAddress((void**)&p_x,   g_x);
    cudaGetSymbolAddress((void**)&p_q,   g_q);
    cudaGetSymbolAddress((void**)&p_pq,  g_pq);
    cudaGetSymbolAddress((void**)&p_pk,  g_pk);
    cudaGetSymbolAddress((void**)&p_pv,  g_pv);
    cudaGetSymbolAddress((void**)&p_ao,  g_ao);
    cudaGetSymbolAddress((void**)&p_t2,  g_t2);
    cudaGetSymbolAddress((void**)&p_off, g_off);
    cudaGetSymbolAddress((void**)&p_aw,  g_aw);
    cudaGetSymbolAddress((void**)&p_val, g_val);
    cudaGetSymbolAddress((void**)&p_ffn, g_ffn);
    cudaGetSymbolAddress((void**)&p_sc,  g_scores);

    const int n_xd = M_Q * D;
    cudaMemcpyAsync(p_x, tgt, sizeof(float) * n_xd, cudaMemcpyDeviceToDevice);

    for (int i = 0; i < NLAYERS; i++) {
        const float* wq = sa_w_q + (size_t)i * D * D;
        const float* bq = sa_b_q + (size_t)i * D;
        const float* wk = sa_w_k + (size_t)i * D * D;
        const float* bk = sa_b_k + (size_t)i * D;
        const float* wv = sa_w_v + (size_t)i * D * D;
        const float* bv = sa_b_v + (size_t)i * D;
        const float* wo = sa_w_o + (size_t)i * D * D;
        const float* bo = sa_b_o + (size_t)i * D;

        // ---- self attention ----
        add_kernel<<<(n_xd + 255) / 256, 256>>>(p_x, qpos, p_q, n_xd);
        gemm(p_q, wq, bq, p_pq, M_Q, D, D, 0);
        gemm(p_q, wk, bk, p_pk, M_Q, D, D, 0);
        gemm(p_x, wv, bv, p_pv, M_Q, D, D, 0);
        attn_scores_kernel<<<dim3(NQ/64, NQ/64, Bq*NH), 256>>>(p_pq, p_pk, p_sc);
        softmax_kernel<<<Bq*NH*NQ, 256>>>(p_sc, NQ);
        attn_pv_kernel<<<dim3(NQ/64, Bq*NH), 256>>>(p_sc, p_pv, p_ao);
        gemm(p_ao, wo, bo, p_t2, M_Q, D, D, 0);
        ln_residual_kernel<<<M_Q, 256>>>(p_x, p_t2, ln2_g + (size_t)i*D, ln2_b + (size_t)i*D, p_x);

        // ---- cross (MS deformable) attention ----
        add_kernel<<<(n_xd + 255) / 256, 256>>>(p_x, qpos, p_q, n_xd);
        gemm(p_q, ca_w_off  + (size_t)i*256*D, ca_b_off  + (size_t)i*256, p_off, M_Q, 256, D, 0);
        gemm(p_q, ca_w_attn + (size_t)i*128*D, ca_b_attn + (size_t)i*128, p_aw,  M_Q, 128, D, 0);
        gemm(src, ca_w_val  + (size_t)i*D*D,   ca_b_val  + (size_t)i*D,   p_val, M_S, D, D, 0);
        ms_deform_kernel<<<M_Q, 256>>>(p_off, p_aw, p_val, refp, p_ao);
        gemm(p_ao, ca_w_out + (size_t)i*D*D, ca_b_out + (size_t)i*D, p_t2, M_Q, D, D, 0);
        ln_residual_kernel<<<M_Q, 256>>>(p_x, p_t2, ln1_g + (size_t)i*D, ln1_b + (size_t)i*D, p_x);

        // ---- FFN ----
        gemm(p_x, ffn_w1 + (size_t)i*DFFN*D, ffn_b1 + (size_t)i*DFFN, p_ffn, M_Q, DFFN, D, 1);
        gemm(p_ffn, ffn_w2 + (size_t)i*D*DFFN, ffn_b2 + (size_t)i*D, p_t2, M_Q, D, DFFN, 0);
        ln_residual_kernel<<<M_Q, 256>>>(p_x, p_t2, ln3_g + (size_t)i*D, ln3_b + (size_t)i*D, p_x);
    }

    cudaMemcpyAsync(d_out, p_x, sizeof(float) * n_xd, cudaMemcpyDeviceToDevice);
}

// round 5
// speedup vs baseline: 1.9558x; 1.9558x over previous
#include <cuda_runtime.h>
#include <math.h>

#define Bq 2
#define NQ 1600
#define D 256
#define NH 8
#define HD 32
#define NL 4
#define NP 4
#define DFFN 1024
#define S_TOT 5440
#define NLAYERS 6
#define M_Q (Bq*NQ)      /* 3200 */
#define M_S (Bq*S_TOT)   /* 10880 */

// ---------------- scratch (device globals; no allocations allowed) ----------
__device__ float g_x[M_Q*D];
__device__ float g_pq[M_Q*D];
__device__ float g_pk[M_Q*D];
__device__ float g_pv[M_Q*D];
__device__ float g_ao[M_Q*D];
__device__ float g_t2[M_Q*D];
__device__ float g_off[M_Q*D];
__device__ float g_aw[M_Q*NH*NL*NP];
__device__ float g_val[M_S*D];
__device__ float g_ffn[M_Q*DFFN];

// ---------------- SGEMM core: C[M,N] = (A+A2)[M,K] @ W[N,K]^T + bias --------
// 64x64 tile, BK=32, 256 threads, 4x4 per thread, float4 everywhere.
// A2 (optional, may be null) is elementwise-added to A during the smem fill.
__device__ __forceinline__ void gemm_tile(const float* __restrict__ A, const float* __restrict__ A2,
                                          const float* __restrict__ W,
                                          const float* __restrict__ bias, float* __restrict__ C,
                                          int M, int N, int K, int relu) {
    __shared__ __align__(16) float As[32][68];
    __shared__ __align__(16) float Ws[32][68];
    int bm = blockIdx.y * 64, bn = blockIdx.x * 64;
    int tid = threadIdx.x;
    int tx = tid & 15, ty = tid >> 4;
    int lr = tid >> 2, l4 = tid & 3;
    float c[4][4] = {};
    const float* Arow = A + (size_t)(bm + lr) * K;
    const float* A2row = A2 ? A2 + (size_t)(bm + lr) * K : 0;
    const float* Wrow = W + (size_t)(bn + lr) * K;
    for (int k0 = 0; k0 < K; k0 += 32) {
        #pragma unroll
        for (int rep = 0; rep < 2; rep++) {
            int kk = (l4 + rep * 4) * 4;
            float4 av = *(const float4*)(Arow + k0 + kk);
            if (A2row) {
                float4 a2 = *(const float4*)(A2row + k0 + kk);
                av.x += a2.x; av.y += a2.y; av.z += a2.z; av.w += a2.w;
            }
            As[kk+0][lr] = av.x; As[kk+1][lr] = av.y; As[kk+2][lr] = av.z; As[kk+3][lr] = av.w;
            float4 wv = *(const float4*)(Wrow + k0 + kk);
            Ws[kk+0][lr] = wv.x; Ws[kk+1][lr] = wv.y; Ws[kk+2][lr] = wv.z; Ws[kk+3][lr] = wv.w;
        }
        __syncthreads();
        #pragma unroll
        for (int k = 0; k < 32; k++) {
            float4 a4 = *(const float4*)&As[k][ty*4];
            float4 b4 = *(const float4*)&Ws[k][tx*4];
            float a[4] = {a4.x, a4.y, a4.z, a4.w};
            float b[4] = {b4.x, b4.y, b4.z, b4.w};
            #pragma unroll
            for (int i = 0; i < 4; i++)
                #pragma unroll
                for (int j = 0; j < 4; j++) c[i][j] = fmaf(a[i], b[j], c[i][j]);
        }
        __syncthreads();
    }
    float4 bv = *(const float4*)&bias[bn + tx*4];
    float bb[4] = {bv.x, bv.y, bv.z, bv.w};
    #pragma unroll
    for (int i = 0; i < 4; i++) {
        int row = bm + ty*4 + i;
        float4 o;
        o.x = c[i][0] + bb[0]; o.y = c[i][1] + bb[1];
        o.z = c[i][2] + bb[2]; o.w = c[i][3] + bb[3];
        if (relu) {
            o.x = fmaxf(o.x, 0.f); o.y = fmaxf(o.y, 0.f);
            o.z = fmaxf(o.z, 0.f); o.w = fmaxf(o.w, 0.f);
        }
        *(float4*)&C[(size_t)row * N + bn + tx*4] = o;
    }
}

__global__ void __launch_bounds__(256) gemm_v2_kernel(const float* __restrict__ A, const float* __restrict__ A2,
                               const float* __restrict__ W,
                               const float* __restrict__ bias, float* __restrict__ C,
                               int M, int N, int K, int relu) {
    gemm_tile(A, A2, W, bias, C, M, N, K, relu);
}

struct Gemm3 {
    const float* A[3];
    const float* A2[3];
    const float* W[3];
    const float* bias[3];
    float* C[3];
};

__global__ void __launch_bounds__(256) gemm3_kernel(Gemm3 g, int M, int N, int K) {
    int z = blockIdx.z;
    gemm_tile(g.A[z], g.A2[z], g.W[z], g.bias[z], g.C[z], M, N, K, 0);
}

// ---------------- fused flash attention (QK^T -> online softmax -> PV) ------
// blockIdx.x: 64-row Q tile (25), blockIdx.y: b*NH+h (16). 256 threads.
__global__ void __launch_bounds__(256, 2) flash_attn_kernel(const float* __restrict__ q,
        const float* __restrict__ k, const float* __restrict__ v, float* __restrict__ out) {
    __shared__ __align__(16) float Qs[32][68];   // [d][i]
    __shared__ __align__(16) float Ks[32][68];   // [d][j]
    __shared__ __align__(16) float Ps[64][68];   // [i][j]
    __shared__ __align__(16) float Vs[64][36];   // [j][c]
    int bh = blockIdx.y; int b = bh >> 3, h = bh & 7;
    int i0 = blockIdx.x * 64;
    int tid = threadIdx.x, tx = tid & 15, ty = tid >> 4;
    int lr = tid >> 2, l4 = tid & 3;
    const float* qb = q + (size_t)b * NQ * D + h * HD;
    const float* kb = k + (size_t)b * NQ * D + h * HD;
    const float* vb = v + (size_t)b * NQ * D + h * HD;
    const float scale = 0.17677669529663687f;   // 1/sqrt(32)

    // load Q tile (pre-scaled), transposed [d][i]
    #pragma unroll
    for (int rep = 0; rep < 2; rep++) {
        int kk = (l4 + rep * 4) * 4;
        float4 qv = *(const float4*)(qb + (size_t)(i0 + lr) * D + kk);
        Qs[kk+0][lr] = qv.x * scale; Qs[kk+1][lr] = qv.y * scale;
        Qs[kk+2][lr] = qv.z * scale; Qs[kk+3][lr] = qv.w * scale;
    }

    float m_i[4], l_i[4], O[4][2];
    #pragma unroll
    for (int i = 0; i < 4; i++) { m_i[i] = -1e30f; l_i[i] = 0.f; O[i][0] = 0.f; O[i][1] = 0.f; }
    int c0 = tx * 2;

    for (int j0 = 0; j0 < NQ; j0 += 64) {
        // load K chunk [d][j] transposed, V chunk [j][c] direct
        #pragma unroll
        for (int rep = 0; rep < 2; rep++) {
            int kk = (l4 + rep * 4) * 4;
            float4 kv = *(const float4*)(kb + (size_t)(j0 + lr) * D + kk);
            Ks[kk+0][lr] = kv.x; Ks[kk+1][lr] = kv.y; Ks[kk+2][lr] = kv.z; Ks[kk+3][lr] = kv.w;
            float4 vv = *(const float4*)(vb + (size_t)(j0 + lr) * D + kk);
            *(float4*)&Vs[lr][kk] = vv;
        }
        __syncthreads();

        // S = Q K^T  (64x64, 4x4 per thread)
        float c[4][4] = {};
        #pragma unroll
        for (int kd = 0; kd < 32; kd++) {
            float4 a4 = *(const float4*)&Qs[kd][ty*4];
            float4 b4 = *(const float4*)&Ks[kd][tx*4];
            float a[4] = {a4.x, a4.y, a4.z, a4.w};
            float bb[4] = {b4.x, b4.y, b4.z, b4.w};
            #pragma unroll
            for (int i = 0; i < 4; i++)
                #pragma unroll
                for (int j = 0; j < 4; j++) c[i][j] = fmaf(a[i], bb[j], c[i][j]);
        }

        // online softmax update, write exp(P) tile to smem
        #pragma unroll
        for (int i = 0; i < 4; i++) {
            float mx = fmaxf(fmaxf(c[i][0], c[i][1]), fmaxf(c[i][2], c[i][3]));
            #pragma unroll
            for (int o = 8; o > 0; o >>= 1) mx = fmaxf(mx, __shfl_xor_sync(0xffffffffu, mx, o));
            float newm = fmaxf(m_i[i], mx);
            float alpha = __expf(m_i[i] - newm);
            m_i[i] = newm;
            float4 e;
            e.x = __expf(c[i][0] - newm); e.y = __expf(c[i][1] - newm);
            e.z = __expf(c[i][2] - newm); e.w = __expf(c[i][3] - newm);
            *(float4*)&Ps[ty*4 + i][tx*4] = e;
            float rs = e.x + e.y + e.z + e.w;
            #pragma unroll
            for (int o = 8; o > 0; o >>= 1) rs += __shfl_xor_sync(0xffffffffu, rs, o);
            l_i[i] = l_i[i] * alpha + rs;
            O[i][0] *= alpha; O[i][1] *= alpha;
        }
        __syncthreads();

        // O += P @ V   (thread: 4 rows x 2 cols)
        #pragma unroll
        for (int j = 0; j < 64; j += 4) {
            float4 p[4]; float2 vv2[4];
            #pragma unroll
            for (int i = 0; i < 4; i++) p[i] = *(const float4*)&Ps[ty*4 + i][j];
            #pragma unroll
            for (int jj = 0; jj < 4; jj++) vv2[jj] = *(const float2*)&Vs[j + jj][c0];
            #pragma unroll
            for (int i = 0; i < 4; i++) {
                O[i][0] = fmaf(p[i].x, vv2[0].x, O[i][0]);
                O[i][0] = fmaf(p[i].y, vv2[1].x, O[i][0]);
                O[i][0] = fmaf(p[i].z, vv2[2].x, O[i][0]);
                O[i][0] = fmaf(p[i].w, vv2[3].x, O[i][0]);
                O[i][1] = fmaf(p[i].x, vv2[0].y, O[i][1]);
                O[i][1] = fmaf(p[i].y, vv2[1].y, O[i][1]);
                O[i][1] = fmaf(p[i].z, vv2[2].y, O[i][1]);
                O[i][1] = fmaf(p[i].w, vv2[3].y, O[i][1]);
            }
        }
        __syncthreads();
    }

    #pragma unroll
    for (int i = 0; i < 4; i++) {
        float inv = 1.f / l_i[i];
        int row = i0 + ty*4 + i;
        float* ob = out + ((size_t)b * NQ + row) * D + h * HD;
        float2 o2; o2.x = O[i][0] * inv; o2.y = O[i][1] * inv;
        *(float2*)&ob[c0] = o2;
    }
}

// ---------------- residual + layernorm: out = LN(x + t) * g + b ----------------
__global__ void ln_residual_kernel(const float* __restrict__ x, const float* __restrict__ t,
                                   const float* __restrict__ gam, const float* __restrict__ bet,
                                   float* __restrict__ out) {
    int row = blockIdx.x;
    int c = threadIdx.x;  // 256 threads = D
    float v = x[(size_t)row * D + c] + t[(size_t)row * D + c];
    __shared__ float redA[8];
    __shared__ float redB[8];
    float s = v;
    #pragma unroll
    for (int o = 16; o > 0; o >>= 1) s += __shfl_xor_sync(0xffffffffu, s, o);
    if ((c & 31) == 0) redA[c >> 5] = s;
    __syncthreads();
    float mu = 0.f;
    #pragma unroll
    for (int i = 0; i < 8; i++) mu += redA[i];
    mu *= (1.f / D);
    float dv = v - mu;
    float sq = dv * dv;
    #pragma unroll
    for (int o = 16; o > 0; o >>= 1) sq += __shfl_xor_sync(0xffffffffu, sq, o);
    if ((c & 31) == 0) redB[c >> 5] = sq;
    __syncthreads();
    float var = 0.f;
    #pragma unroll
    for (int i = 0; i < 8; i++) var += redB[i];
    var *= (1.f / D);
    out[(size_t)row * D + c] = dv * rsqrtf(var + 1e-5f) * gam[c] + bet[c];
}

// ---------------- multi-scale deformable sampling ----------------
__global__ void ms_deform_kernel(const float* __restrict__ off, const float* __restrict__ aw_raw,
                                 const float* __restrict__ value, const float* __restrict__ refp,
                                 float* __restrict__ out) {
    const int lvl_start[4] = {0, 4096, 5120, 5376};
    const int lvl_w[4] = {64, 32, 16, 8};
    int row = blockIdx.x;
    int b = row / NQ; int q = row % NQ;
    int tid = threadIdx.x;
    int h = tid >> 5, lane = tid & 31;
    const float* awr = aw_raw + (size_t)row * (NH * 16) + h * 16;
    float a = (lane < 16) ? awr[lane] : -1e30f;
    float m = a;
    #pragma unroll
    for (int o = 16; o > 0; o >>= 1) m = fmaxf(m, __shfl_xor_sync(0xffffffffu, m, o));
    float e = (lane < 16) ? __expf(a - m) : 0.f;
    float ssum = e;
    #pragma unroll
    for (int o = 16; o > 0; o >>= 1) ssum += __shfl_xor_sync(0xffffffffu, ssum, o);
    float awn = e / ssum;
    const float* offr = off + (size_t)row * D + h * (NL * NP * 2);
    float acc = 0.f;
    #pragma unroll
    for (int l = 0; l < NL; l++) {
        int Wl = lvl_w[l]; int Hl = Wl;
        float rx = refp[(((size_t)b * NQ + q) * NL + l) * 2 + 0];
        float ry = refp[(((size_t)b * NQ + q) * NL + l) * 2 + 1];
        const float* vbase = value + ((size_t)b * S_TOT + lvl_start[l]) * D + h * HD + lane;
        #pragma unroll
        for (int p = 0; p < NP; p++) {
            float ox = offr[(l * NP + p) * 2 + 0];
            float oy = offr[(l * NP + p) * 2 + 1];
            float xx = (rx + ox / (float)Wl) * (float)Wl - 0.5f;
            float yy = (ry + oy / (float)Hl) * (float)Hl - 0.5f;
            float x0f = floorf(xx), y0f = floorf(yy);
            int x0 = (int)x0f, y0 = (int)y0f;
            float wx1 = xx - x0f, wy1 = yy - y0f;
            float pv = 0.f;
            #pragma unroll
            for (int dy = 0; dy < 2; dy++) {
                #pragma unroll
                for (int dx = 0; dx < 2; dx++) {
                    int xi = x0 + dx, yi = y0 + dy;
                    float w = (dx ? wx1 : 1.f - wx1) * (dy ? wy1 : 1.f - wy1);
                    if (xi >= 0 && xi < Wl && yi >= 0 && yi < Hl)
                        pv = fmaf(w, vbase[(size_t)(yi * Wl + xi) * D], pv);
                }
            }
            float awv = __shfl_sync(0xffffffffu, awn, l * NP + p);
            acc = fmaf(pv, awv, acc);
        }
    }
    out[(size_t)row * D + h * HD + lane] = acc;
}

// ---------------- host orchestration ----------------
static inline void gemm(const float* A, const float* A2, const float* W, const float* bias,
                        float* C, int M, int N, int K, int relu) {
    dim3 grid(N / 64, M / 64);
    gemm_v2_kernel<<<grid, 256>>>(A, A2, W, bias, C, M, N, K, relu);
}

extern "C" void kernel_launch(void* const* d_in, const int* in_sizes, int n_in,
                              void* d_out, int out_size) {
    const float* tgt   = (const float*)d_in[0];
    const float* qpos  = (const float*)d_in[1];
    const float* refp  = (const float*)d_in[2];
    const float* src   = (const float*)d_in[3];
    const float* sa_w_q = (const float*)d_in[4];
    const float* sa_b_q = (const float*)d_in[5];
    const float* sa_w_k = (const float*)d_in[6];
    const float* sa_b_k = (const float*)d_in[7];
    const float* sa_w_v = (const float*)d_in[8];
    const float* sa_b_v = (const float*)d_in[9];
    const float* sa_w_o = (const float*)d_in[10];
    const float* sa_b_o = (const float*)d_in[11];
    const float* ln2_g  = (const float*)d_in[12];
    const float* ln2_b  = (const float*)d_in[13];
    const float* ca_w_off  = (const float*)d_in[14];
    const float* ca_b_off  = (const float*)d_in[15];
    const float* ca_w_attn = (const float*)d_in[16];
    const float* ca_b_attn = (const float*)d_in[17];
    const float* ca_w_val  = (const float*)d_in[18];
    const float* ca_b_val  = (const float*)d_in[19];
    const float* ca_w_out  = (const float*)d_in[20];
    const float* ca_b_out  = (const float*)d_in[21];
    const float* ln1_g  = (const float*)d_in[22];
    const float* ln1_b  = (const float*)d_in[23];
    const float* ffn_w1 = (const float*)d_in[24];
    const float* ffn_b1 = (const float*)d_in[25];
    const float* ffn_w2 = (const float*)d_in[26];
    const float* ffn_b2 = (const float*)d_in[27];
    const float* ln3_g  = (const float*)d_in[28];
    const float* ln3_b  = (const float*)d_in[29];

    float *p_x, *p_pq, *p_pk, *p_pv, *p_ao, *p_t2, *p_off, *p_aw, *p_val, *p_ffn;
    cudaGetSymbolAddress((void**)&p_x,   g_x);
    cudaGetSymbolAddress((void**)&p_pq,  g_pq);
    cudaGetSymbolAddress((void**)&p_pk,  g_pk);
    cudaGetSymbolAddress((void**)&p_pv,  g_pv);
    cudaGetSymbolAddress((void**)&p_ao,  g_ao);
    cudaGetSymbolAddress((void**)&p_t2,  g_t2);
    cudaGetSymbolAddress((void**)&p_off, g_off);
    cudaGetSymbolAddress((void**)&p_aw,  g_aw);
    cudaGetSymbolAddress((void**)&p_val, g_val);
    cudaGetSymbolAddress((void**)&p_ffn, g_ffn);

    const int n_xd = M_Q * D;
    cudaMemcpyAsync(p_x, tgt, sizeof(float) * n_xd, cudaMemcpyDeviceToDevice);

    for (int i = 0; i < NLAYERS; i++) {
        const float* wq = sa_w_q + (size_t)i * D * D;
        const float* bq = sa_b_q + (size_t)i * D;
        const float* wk = sa_w_k + (size_t)i * D * D;
        const float* bk = sa_b_k + (size_t)i * D;
        const float* wv = sa_w_v + (size_t)i * D * D;
        const float* bv = sa_b_v + (size_t)i * D;
        const float* wo = sa_w_o + (size_t)i * D * D;
        const float* bo = sa_b_o + (size_t)i * D;

        // ---- self attention (q = x + qpos fused into GEMM A-load) ----
        Gemm3 g3;
        g3.A[0] = p_x;  g3.A[1] = p_x;  g3.A[2] = p_x;
        g3.A2[0] = qpos; g3.A2[1] = qpos; g3.A2[2] = 0;
        g3.W[0] = wq;  g3.W[1] = wk;  g3.W[2] = wv;
        g3.bias[0] = bq; g3.bias[1] = bk; g3.bias[2] = bv;
        g3.C[0] = p_pq; g3.C[1] = p_pk; g3.C[2] = p_pv;
        gemm3_kernel<<<dim3(D/64, M_Q/64, 3), 256>>>(g3, M_Q, D, D);
        flash_attn_kernel<<<dim3(NQ/64, Bq*NH), 256>>>(p_pq, p_pk, p_pv, p_ao);
        gemm(p_ao, 0, wo, bo, p_t2, M_Q, D, D, 0);
        ln_residual_kernel<<<M_Q, 256>>>(p_x, p_t2, ln2_g + (size_t)i*D, ln2_b + (size_t)i*D, p_x);

        // ---- cross (MS deformable) attention ----
        gemm(p_x, qpos, ca_w_off  + (size_t)i*256*D, ca_b_off  + (size_t)i*256, p_off, M_Q, 256, D, 0);
        gemm(p_x, qpos, ca_w_attn + (size_t)i*128*D, ca_b_attn + (size_t)i*128, p_aw,  M_Q, 128, D, 0);
        gemm(src, 0,    ca_w_val  + (size_t)i*D*D,   ca_b_val  + (size_t)i*D,   p_val, M_S, D, D, 0);
        ms_deform_kernel<<<M_Q, 256>>>(p_off, p_aw, p_val, refp, p_ao);
        gemm(p_ao, 0, ca_w_out + (size_t)i*D*D, ca_b_out + (size_t)i*D, p_t2, M_Q, D, D, 0);
        ln_residual_kernel<<<M_Q, 256>>>(p_x, p_t2, ln1_g + (size_t)i*D, ln1_b + (size_t)i*D, p_x);

        // ---- FFN ----
        gemm(p_x, 0, ffn_w1 + (size_t)i*DFFN*D, ffn_b1 + (size_t)i*DFFN, p_ffn, M_Q, DFFN, D, 1);
        gemm(p_ffn, 0, ffn_w2 + (size_t)i*D*DFFN, ffn_b2 + (size_t)i*D, p_t2, M_Q, D, DFFN, 0);
        ln_residual_kernel<<<M_Q, 256>>>(p_x, p_t2, ln3_g + (size_t)i*D, ln3_b + (size_t)i*D, p_x);
    }

    cudaMemcpyAsync(d_out, p_x, sizeof(float) * n_xd, cudaMemcpyDeviceToDevice);
}